// round 5
// baseline (speedup 1.0000x reference)
#include <cuda_runtime.h>
#include <math.h>

#define Kc 16
#define Mc 32
#define PK (Mc * Kc * Kc)        /* 8192  */
#define PTOT (3 * PK + Kc)       /* 24592 */
#define SMEM_BYTES (PTOT * 4)    /* 98368 */

// Precomputed params, transposed layout [i][j][k] (k fastest):
//   [0,PK)     A = s/sigma              (s = sqrt(log2e/2))
//   [PK,2PK)   B = -s*mu/sigma
//   [2PK,3PK)  C = (logW - log(sigma) - 0.5*log(2pi)) * log2e
//   [3PK,+K)   w = softmax(wk0_logits)
__device__ __align__(16) float g_P[PTOT];

__global__ void prep_kernel(const float* __restrict__ wk0,
                            const float* __restrict__ W,
                            const float* __restrict__ mu,
                            const float* __restrict__ ps) {
    int idx = blockIdx.x * blockDim.x + threadIdx.x;
    if (idx >= PK) return;
    int i = idx >> 8;
    int k = (idx >> 4) & 15;
    int j = idx & 15;

    // log_softmax over axis=1 (the k index) of W_logits[i, :, j]
    int base = i * 256 + j;
    float m = -1e30f;
#pragma unroll
    for (int kk = 0; kk < Kc; kk++) m = fmaxf(m, W[base + kk * 16]);
    float ssum = 0.f;
#pragma unroll
    for (int kk = 0; kk < Kc; kk++) ssum += expf(W[base + kk * 16] - m);
    float logW = W[idx] - m - logf(ssum);

    float p = ps[idx];
    float sigma = (p > 20.f) ? p : log1pf(expf(p));   // softplus
    float inv = 1.f / sigma;
    float log_sigma = logf(sigma);

    const float LOG2E = 1.4426950408889634f;
    const float HALF_LOG_2PI = 0.9189385332046727f;
    const float S = 0.84932180028801907f;  // sqrt(LOG2E/2)

    int o = i * 256 + j * 16 + k;          // transposed [i][j][k]
    g_P[o]          = S * inv;
    g_P[PK + o]     = -S * mu[idx] * inv;
    g_P[2 * PK + o] = (logW - log_sigma - HALF_LOG_2PI) * LOG2E;

    if (idx < Kc) {
        float mw = -1e30f;
#pragma unroll
        for (int kk = 0; kk < Kc; kk++) mw = fmaxf(mw, wk0[kk]);
        float sw = 0.f;
#pragma unroll
        for (int kk = 0; kk < Kc; kk++) sw += expf(wk0[kk] - mw);
        g_P[3 * PK + idx] = expf(wk0[idx] - mw) / sw;
    }
}

__device__ __forceinline__ float ex2_approx(float t) {
    float r;
    asm("ex2.approx.ftz.f32 %0, %1;" : "=f"(r) : "f"(t));
    return r;
}

__global__ void __launch_bounds__(256, 2)
ttg_main(const float* __restrict__ X, float* __restrict__ out, int N) {
    extern __shared__ float sm[];
    {
        const float4* src = (const float4*)g_P;
        float4* dst = (float4*)sm;
        for (int t = threadIdx.x; t < PTOT / 4; t += blockDim.x) dst[t] = src[t];
    }
    __syncthreads();

    int n = blockIdx.x * blockDim.x + threadIdx.x;
    if (n >= N) return;

    // Each sample's X row is exactly one 128B line; pull it into registers.
    float x[Mc];
    const float4* Xv = (const float4*)(X + (size_t)n * Mc);
#pragma unroll
    for (int q = 0; q < Mc / 4; q++) {
        float4 t4 = Xv[q];
        x[4 * q + 0] = t4.x; x[4 * q + 1] = t4.y;
        x[4 * q + 2] = t4.z; x[4 * q + 3] = t4.w;
    }

    float v[Kc];
#pragma unroll
    for (int k = 0; k < Kc; k++) v[k] = sm[3 * PK + k];

    const float4* s4 = (const float4*)sm;

#pragma unroll 1
    for (int i = 0; i < Mc; i++) {
        float xi = x[i];
        float vn[Kc];
#pragma unroll
        for (int k = 0; k < Kc; k++) vn[k] = 0.f;
        int ib = i * 64;  // float4 index of row block i
#pragma unroll
        for (int j = 0; j < Kc; j++) {
            float vj = v[j];
            int jb = ib + j * 4;
#pragma unroll
            for (int q = 0; q < 4; q++) {
                float4 a = s4[jb + q];
                float4 b = s4[2048 + jb + q];
                float4 c = s4[4096 + jb + q];
                float z0 = fmaf(xi, a.x, b.x);
                float z1 = fmaf(xi, a.y, b.y);
                float z2 = fmaf(xi, a.z, b.z);
                float z3 = fmaf(xi, a.w, b.w);
                float t0 = fmaf(z0, -z0, c.x);
                float t1 = fmaf(z1, -z1, c.y);
                float t2 = fmaf(z2, -z2, c.z);
                float t3 = fmaf(z3, -z3, c.w);
                float r0 = ex2_approx(t0);
                float r1 = ex2_approx(t1);
                float r2 = ex2_approx(t2);
                float r3 = ex2_approx(t3);
                vn[4 * q + 0] = fmaf(r0, vj, vn[4 * q + 0]);
                vn[4 * q + 1] = fmaf(r1, vj, vn[4 * q + 1]);
                vn[4 * q + 2] = fmaf(r2, vj, vn[4 * q + 2]);
                vn[4 * q + 3] = fmaf(r3, vj, vn[4 * q + 3]);
            }
        }
#pragma unroll
        for (int k = 0; k < Kc; k++) v[k] = vn[k];
    }

    float s = 0.f;
#pragma unroll
    for (int k = 0; k < Kc; k++) s += v[k];
    out[n] = logf(s + 2.2204460492503131e-16f);
}

extern "C" void kernel_launch(void* const* d_in, const int* in_sizes, int n_in,
                              void* d_out, int out_size) {
    const float* X   = (const float*)d_in[0];
    const float* wk0 = (const float*)d_in[1];
    const float* W   = (const float*)d_in[2];
    const float* mu  = (const float*)d_in[3];
    const float* ps  = (const float*)d_in[4];
    float* out = (float*)d_out;
    int N = out_size;

    cudaFuncSetAttribute((const void*)ttg_main,
                         cudaFuncAttributeMaxDynamicSharedMemorySize, SMEM_BYTES);

    prep_kernel<<<(PK + 255) / 256, 256>>>(wk0, W, mu, ps);
    ttg_main<<<(N + 255) / 256, 256, SMEM_BYTES>>>(X, out, N);
}

// round 6
// speedup vs baseline: 1.0011x; 1.0011x over previous
#include <cuda_runtime.h>
#include <math.h>

#define Kc 16
#define Mc 32
#define PK (Mc * Kc * Kc)        /* 8192  */
#define PTOT (3 * PK + Kc)       /* 24592 */
#define SMEM_BYTES (PTOT * 4)    /* 98368 */

// Precomputed params, transposed layout [i][j][k] (k fastest):
//   [0,PK)     A = s/sigma              (s = sqrt(log2e/2))
//   [PK,2PK)   B = -s*mu/sigma
//   [2PK,3PK)  C = (logW - log(sigma) - 0.5*log(2pi)) * log2e
//   [3PK,+K)   w = softmax(wk0_logits)
__device__ __align__(16) float g_P[PTOT];

__global__ void prep_kernel(const float* __restrict__ wk0,
                            const float* __restrict__ W,
                            const float* __restrict__ mu,
                            const float* __restrict__ ps) {
    int idx = blockIdx.x * blockDim.x + threadIdx.x;
    if (idx >= PK) return;
    int i = idx >> 8;
    int k = (idx >> 4) & 15;
    int j = idx & 15;

    // log_softmax over axis=1 (the k index) of W_logits[i, :, j]
    int base = i * 256 + j;
    float m = -1e30f;
#pragma unroll
    for (int kk = 0; kk < Kc; kk++) m = fmaxf(m, W[base + kk * 16]);
    float ssum = 0.f;
#pragma unroll
    for (int kk = 0; kk < Kc; kk++) ssum += expf(W[base + kk * 16] - m);
    float logW = W[idx] - m - logf(ssum);

    float p = ps[idx];
    float sigma = (p > 20.f) ? p : log1pf(expf(p));   // softplus
    float inv = 1.f / sigma;
    float log_sigma = logf(sigma);

    const float LOG2E = 1.4426950408889634f;
    const float HALF_LOG_2PI = 0.9189385332046727f;
    const float S = 0.84932180028801907f;  // sqrt(LOG2E/2)

    int o = i * 256 + j * 16 + k;          // transposed [i][j][k]
    g_P[o]          = S * inv;
    g_P[PK + o]     = -S * mu[idx] * inv;
    g_P[2 * PK + o] = (logW - log_sigma - HALF_LOG_2PI) * LOG2E;

    if (idx < Kc) {
        float mw = -1e30f;
#pragma unroll
        for (int kk = 0; kk < Kc; kk++) mw = fmaxf(mw, wk0[kk]);
        float sw = 0.f;
#pragma unroll
        for (int kk = 0; kk < Kc; kk++) sw += expf(wk0[kk] - mw);
        g_P[3 * PK + idx] = expf(wk0[idx] - mw) / sw;
    }
}

__device__ __forceinline__ float ex2_approx(float t) {
    float r;
    asm("ex2.approx.ftz.f32 %0, %1;" : "=f"(r) : "f"(t));
    return r;
}

__global__ void __launch_bounds__(256, 2)
ttg_main(const float* __restrict__ X, float* __restrict__ out, int N) {
    extern __shared__ float sm[];
    {
        const float4* src = (const float4*)g_P;
        float4* dst = (float4*)sm;
        for (int t = threadIdx.x; t < PTOT / 4; t += blockDim.x) dst[t] = src[t];
    }
    __syncthreads();

    int n = blockIdx.x * blockDim.x + threadIdx.x;
    if (n >= N) return;

    // Each sample's X row is exactly one 128B line; pull it into registers.
    float x[Mc];
    const float4* Xv = (const float4*)(X + (size_t)n * Mc);
#pragma unroll
    for (int q = 0; q < Mc / 4; q++) {
        float4 t4 = Xv[q];
        x[4 * q + 0] = t4.x; x[4 * q + 1] = t4.y;
        x[4 * q + 2] = t4.z; x[4 * q + 3] = t4.w;
    }

    float v[Kc];
#pragma unroll
    for (int k = 0; k < Kc; k++) v[k] = sm[3 * PK + k];

    const float4* s4 = (const float4*)sm;

#pragma unroll 1
    for (int i = 0; i < Mc; i++) {
        float xi = x[i];
        float vn[Kc];
#pragma unroll
        for (int k = 0; k < Kc; k++) vn[k] = 0.f;
        int ib = i * 64;  // float4 index of row block i
#pragma unroll
        for (int j = 0; j < Kc; j++) {
            float vj = v[j];
            int jb = ib + j * 4;
#pragma unroll
            for (int q = 0; q < 4; q++) {
                float4 a = s4[jb + q];
                float4 b = s4[2048 + jb + q];
                float4 c = s4[4096 + jb + q];
                float z0 = fmaf(xi, a.x, b.x);
                float z1 = fmaf(xi, a.y, b.y);
                float z2 = fmaf(xi, a.z, b.z);
                float z3 = fmaf(xi, a.w, b.w);
                float t0 = fmaf(z0, -z0, c.x);
                float t1 = fmaf(z1, -z1, c.y);
                float t2 = fmaf(z2, -z2, c.z);
                float t3 = fmaf(z3, -z3, c.w);
                float r0 = ex2_approx(t0);
                float r1 = ex2_approx(t1);
                float r2 = ex2_approx(t2);
                float r3 = ex2_approx(t3);
                vn[4 * q + 0] = fmaf(r0, vj, vn[4 * q + 0]);
                vn[4 * q + 1] = fmaf(r1, vj, vn[4 * q + 1]);
                vn[4 * q + 2] = fmaf(r2, vj, vn[4 * q + 2]);
                vn[4 * q + 3] = fmaf(r3, vj, vn[4 * q + 3]);
            }
        }
#pragma unroll
        for (int k = 0; k < Kc; k++) v[k] = vn[k];
    }

    float s = 0.f;
#pragma unroll
    for (int k = 0; k < Kc; k++) s += v[k];
    out[n] = logf(s + 2.2204460492503131e-16f);
}

extern "C" void kernel_launch(void* const* d_in, const int* in_sizes, int n_in,
                              void* d_out, int out_size) {
    const float* X   = (const float*)d_in[0];
    const float* wk0 = (const float*)d_in[1];
    const float* W   = (const float*)d_in[2];
    const float* mu  = (const float*)d_in[3];
    const float* ps  = (const float*)d_in[4];
    float* out = (float*)d_out;
    int N = out_size;

    cudaFuncSetAttribute((const void*)ttg_main,
                         cudaFuncAttributeMaxDynamicSharedMemorySize, SMEM_BYTES);

    prep_kernel<<<(PK + 255) / 256, 256>>>(wk0, W, mu, ps);
    ttg_main<<<(N + 255) / 256, 256, SMEM_BYTES>>>(X, out, N);
}

// round 7
// speedup vs baseline: 1.0044x; 1.0033x over previous
#include <cuda_runtime.h>
#include <math.h>

#define Kc 16
#define Mc 32
#define PK (Mc * Kc * Kc)        /* 8192  */
#define PTOT (3 * PK + Kc)       /* 24592 */
#define SMEM_BYTES (PTOT * 4)    /* 98368 */

// Precomputed params, transposed layout [i][j][k] (k fastest):
//   [0,PK)     A = s/sigma              (s = sqrt(log2e/2))
//   [PK,2PK)   B = -s*mu/sigma
//   [2PK,3PK)  C = (logW - log(sigma) - 0.5*log(2pi)) * log2e
//   [3PK,+K)   w = softmax(wk0_logits)
__device__ __align__(16) float g_P[PTOT];

__global__ void prep_kernel(const float* __restrict__ wk0,
                            const float* __restrict__ W,
                            const float* __restrict__ mu,
                            const float* __restrict__ ps) {
    int idx = blockIdx.x * blockDim.x + threadIdx.x;
    if (idx >= PK) return;
    int i = idx >> 8;
    int k = (idx >> 4) & 15;
    int j = idx & 15;

    // log_softmax over axis=1 (the k index) of W_logits[i, :, j]
    int base = i * 256 + j;
    float m = -1e30f;
#pragma unroll
    for (int kk = 0; kk < Kc; kk++) m = fmaxf(m, W[base + kk * 16]);
    float ssum = 0.f;
#pragma unroll
    for (int kk = 0; kk < Kc; kk++) ssum += expf(W[base + kk * 16] - m);
    float logW = W[idx] - m - logf(ssum);

    float p = ps[idx];
    float sigma = (p > 20.f) ? p : log1pf(expf(p));   // softplus
    float inv = 1.f / sigma;
    float log_sigma = logf(sigma);

    const float LOG2E = 1.4426950408889634f;
    const float HALF_LOG_2PI = 0.9189385332046727f;
    const float S = 0.84932180028801907f;  // sqrt(LOG2E/2)

    int o = i * 256 + j * 16 + k;          // transposed [i][j][k]
    g_P[o]          = S * inv;
    g_P[PK + o]     = -S * mu[idx] * inv;
    g_P[2 * PK + o] = (logW - log_sigma - HALF_LOG_2PI) * LOG2E;

    if (idx < Kc) {
        float mw = -1e30f;
#pragma unroll
        for (int kk = 0; kk < Kc; kk++) mw = fmaxf(mw, wk0[kk]);
        float sw = 0.f;
#pragma unroll
        for (int kk = 0; kk < Kc; kk++) sw += expf(wk0[kk] - mw);
        g_P[3 * PK + idx] = expf(wk0[idx] - mw) / sw;
    }
}

__device__ __forceinline__ float ex2_approx(float t) {
    float r;
    asm("ex2.approx.ftz.f32 %0, %1;" : "=f"(r) : "f"(t));
    return r;
}

__global__ void __launch_bounds__(256, 2)
ttg_main(const float* __restrict__ X, float* __restrict__ out, int N) {
    extern __shared__ float sm[];
    {
        const float4* src = (const float4*)g_P;
        float4* dst = (float4*)sm;
        for (int t = threadIdx.x; t < PTOT / 4; t += blockDim.x) dst[t] = src[t];
    }
    __syncthreads();

    int n = blockIdx.x * blockDim.x + threadIdx.x;
    if (n >= N) return;

    // Each sample's X row is exactly one 128B line; pull it into registers.
    float x[Mc];
    const float4* Xv = (const float4*)(X + (size_t)n * Mc);
#pragma unroll
    for (int q = 0; q < Mc / 4; q++) {
        float4 t4 = Xv[q];
        x[4 * q + 0] = t4.x; x[4 * q + 1] = t4.y;
        x[4 * q + 2] = t4.z; x[4 * q + 3] = t4.w;
    }

    float v[Kc];
#pragma unroll
    for (int k = 0; k < Kc; k++) v[k] = sm[3 * PK + k];

    const float4* s4 = (const float4*)sm;

#pragma unroll 1
    for (int i = 0; i < Mc; i++) {
        float xi = x[i];
        float vn[Kc];
#pragma unroll
        for (int k = 0; k < Kc; k++) vn[k] = 0.f;
        int ib = i * 64;  // float4 index of row block i
#pragma unroll
        for (int j = 0; j < Kc; j++) {
            float vj = v[j];
            int jb = ib + j * 4;
#pragma unroll
            for (int q = 0; q < 4; q++) {
                float4 a = s4[jb + q];
                float4 b = s4[2048 + jb + q];
                float4 c = s4[4096 + jb + q];
                float z0 = fmaf(xi, a.x, b.x);
                float z1 = fmaf(xi, a.y, b.y);
                float z2 = fmaf(xi, a.z, b.z);
                float z3 = fmaf(xi, a.w, b.w);
                float t0 = fmaf(z0, -z0, c.x);
                float t1 = fmaf(z1, -z1, c.y);
                float t2 = fmaf(z2, -z2, c.z);
                float t3 = fmaf(z3, -z3, c.w);
                float r0 = ex2_approx(t0);
                float r1 = ex2_approx(t1);
                float r2 = ex2_approx(t2);
                float r3 = ex2_approx(t3);
                vn[4 * q + 0] = fmaf(r0, vj, vn[4 * q + 0]);
                vn[4 * q + 1] = fmaf(r1, vj, vn[4 * q + 1]);
                vn[4 * q + 2] = fmaf(r2, vj, vn[4 * q + 2]);
                vn[4 * q + 3] = fmaf(r3, vj, vn[4 * q + 3]);
            }
        }
#pragma unroll
        for (int k = 0; k < Kc; k++) v[k] = vn[k];
    }

    float s = 0.f;
#pragma unroll
    for (int k = 0; k < Kc; k++) s += v[k];
    out[n] = logf(s + 2.2204460492503131e-16f);
}

extern "C" void kernel_launch(void* const* d_in, const int* in_sizes, int n_in,
                              void* d_out, int out_size) {
    const float* X   = (const float*)d_in[0];
    const float* wk0 = (const float*)d_in[1];
    const float* W   = (const float*)d_in[2];
    const float* mu  = (const float*)d_in[3];
    const float* ps  = (const float*)d_in[4];
    float* out = (float*)d_out;
    int N = out_size;

    cudaFuncSetAttribute((const void*)ttg_main,
                         cudaFuncAttributeMaxDynamicSharedMemorySize, SMEM_BYTES);

    prep_kernel<<<(PK + 255) / 256, 256>>>(wk0, W, mu, ps);
    ttg_main<<<(N + 255) / 256, 256, SMEM_BYTES>>>(X, out, N);
}